// round 1
// baseline (speedup 1.0000x reference)
#include <cuda_runtime.h>

// Reference math:
//   h = MLP(concat(x[src], x[dst]))            -> [E, 1]
//   out = LayerNorm_{dim=1}(h) * gamma + beta
// With a normalized dim of size 1: mu == h exactly, (h - mu) == 0 exactly,
// var == 0 exactly, so out == ln_beta broadcast over [E, 1] — bit-exact.
// The entire gather + 4-layer MLP is algebraically dead code.
//
// Therefore the optimal kernel is a vectorized fill of d_out with ln_beta[0].

__global__ void decoder_fill_kernel(const float* __restrict__ ln_beta,
                                    float* __restrict__ out,
                                    int n) {
    const float b = ln_beta[0];

    // Vectorized body: float4 stores.
    int n4 = n >> 2;  // number of float4 elements
    float4 v = make_float4(b, b, b, b);
    float4* out4 = reinterpret_cast<float4*>(out);

    for (int i = blockIdx.x * blockDim.x + threadIdx.x;
         i < n4;
         i += gridDim.x * blockDim.x) {
        out4[i] = v;
    }

    // Scalar tail (n not divisible by 4).
    int tail_start = n4 << 2;
    for (int i = tail_start + blockIdx.x * blockDim.x + threadIdx.x;
         i < n;
         i += gridDim.x * blockDim.x) {
        out[i] = b;
    }
}

extern "C" void kernel_launch(void* const* d_in, const int* in_sizes, int n_in,
                              void* d_out, int out_size) {
    // Input order (metadata): x_node, edge_index, W1, b1, W2, b2, W3, b3,
    //                         W4, b4, ln_gamma, ln_beta
    const float* ln_beta = (const float*)d_in[n_in - 1];
    float* out = (float*)d_out;

    // 12.8 MB of stores: a few waves of modest CTAs saturates HBM write BW.
    const int threads = 256;
    int blocks = 148 * 4;  // 592 CTAs, grid-stride covers 800k float4 stores
    decoder_fill_kernel<<<blocks, threads>>>(ln_beta, out, out_size);
}